// round 3
// baseline (speedup 1.0000x reference)
#include <cuda_runtime.h>
#include <cuda_bf16.h>
#include <cstdint>

#define NUM_USER 200000
#define NUM_QUESTION 20000
#define NUM_CONCEPT 128
#define DIM_HIDDEN 512
#define H2 256
#define BATCH 16384
#define EMAX 400

// ---------------- scratch (device globals; no allocations allowed) ----------
__device__ float g_bpT[NUM_CONCEPT * BATCH];     // sigmoid(priori) feature-major [k][b]
__device__ float g_cpT[EMAX * BATCH];            // pow(sigmoid(condi_p),1/l) [e][b]
__device__ float g_cnT[EMAX * BATCH];
__device__ float g_qT[NUM_CONCEPT * BATCH];      // q gathered, feature-major [k][b]
__device__ float g_AuT[NUM_CONCEPT * BATCH];     // post*q, feature-major
__device__ float g_AiT[NUM_CONCEPT * BATCH];     // sigmoid(diff)*q, feature-major
__device__ float g_disc[BATCH];
__device__ float g_XT[DIM_HIDDEN * BATCH];       // layer-1 output, feature-major
__device__ float g_H[BATCH * H2];                // layer-2 output, row-major

// ---------------- graph structure (replicated numpy RandomState(0)) ---------
struct Graph {
    int E;
    unsigned char lp[NUM_CONCEPT];
    short off[NUM_CONCEPT];
    unsigned char pred[NUM_CONCEPT][3];
};
struct EdgeParams {
    int E;
    float invl[EMAX];
};

struct MT19937 {
    uint32_t mt[624];
    int mti;
    void seed(uint32_t s) {
        mt[0] = s;
        for (int i = 1; i < 624; i++)
            mt[i] = 1812433253u * (mt[i - 1] ^ (mt[i - 1] >> 30)) + (uint32_t)i;
        mti = 624;
    }
    uint32_t next() {
        if (mti >= 624) {
            for (int i = 0; i < 624; i++) {
                uint32_t y = (mt[i] & 0x80000000u) | (mt[(i + 1) % 624] & 0x7fffffffu);
                uint32_t v = mt[(i + 397) % 624] ^ (y >> 1);
                if (y & 1u) v ^= 0x9908b0dfu;
                mt[i] = v;
            }
            mti = 0;
        }
        uint32_t y = mt[mti++];
        y ^= y >> 11;
        y ^= (y << 7) & 0x9d2c5680u;
        y ^= (y << 15) & 0xefc60000u;
        y ^= y >> 18;
        return y;
    }
    uint32_t interval(uint32_t mx) {
        if (mx == 0) return 0;
        uint32_t mask = mx;
        mask |= mask >> 1; mask |= mask >> 2; mask |= mask >> 4;
        mask |= mask >> 8; mask |= mask >> 16;
        uint32_t v;
        do { v = next() & mask; } while (v > mx);
        return v;
    }
};

static void build_graph(Graph& g, EdgeParams& ep) {
    MT19937 r;
    r.seed(0u);
    int E = 0;
    for (int k = 0; k < NUM_CONCEPT; k++) {
        int l = 0;
        if (k > 0) {
            int hi = (k < 3) ? k : 3;
            l = (int)r.interval((uint32_t)hi);
        }
        g.lp[k] = (unsigned char)l;
        g.off[k] = (short)E;
        g.pred[k][0] = g.pred[k][1] = g.pred[k][2] = 0;
        if (l > 0) {
            int perm[NUM_CONCEPT];
            for (int i = 0; i < k; i++) perm[i] = i;
            for (int i = k - 1; i >= 1; i--) {
                int j = (int)r.interval((uint32_t)i);
                int t = perm[i]; perm[i] = perm[j]; perm[j] = t;
            }
            int p[3];
            for (int j = 0; j < l; j++) p[j] = perm[j];
            for (int a = 0; a < l; a++)
                for (int b = a + 1; b < l; b++)
                    if (p[b] < p[a]) { int t = p[a]; p[a] = p[b]; p[b] = t; }
            for (int j = 0; j < l; j++) {
                g.pred[k][j] = (unsigned char)p[j];
                ep.invl[E + j] = 1.0f / (float)l;
            }
        }
        E += l;
    }
    g.E = E;
    ep.E = E;
}

// ---------------- device helpers --------------------------------------------
__device__ __forceinline__ float sigmoidf(float x) {
    return 1.0f / (1.0f + __expf(-x));
}
__device__ __forceinline__ float to_tf32(float x) {
    unsigned u;
    asm("cvt.rna.tf32.f32 %0, %1;" : "=r"(u) : "f"(x));
    return __uint_as_float(u);
}
__device__ __forceinline__ void mma_tf32(float* c, const unsigned* a, const unsigned* b) {
    asm volatile(
        "mma.sync.aligned.m16n8k8.row.col.f32.tf32.tf32.f32 "
        "{%0,%1,%2,%3}, {%4,%5,%6,%7}, {%8,%9}, {%0,%1,%2,%3};\n"
        : "+f"(c[0]), "+f"(c[1]), "+f"(c[2]), "+f"(c[3])
        : "r"(a[0]), "r"(a[1]), "r"(a[2]), "r"(a[3]), "r"(b[0]), "r"(b[1]));
}

// ---------------- kernel A: elementwise precompute + transposes -------------
// Block handles 32 batch elements; 256 threads. All outputs feature-major.
// dyn smem: 3 buffers of 128*33 floats (phase 1), reused as 2 buffers (phase 2)
__global__ __launch_bounds__(256) void precompute_kernel(
    EdgeParams ep,
    const int* __restrict__ user_id, const int* __restrict__ question_id,
    const float* __restrict__ priori, const float* __restrict__ condi_p,
    const float* __restrict__ condi_n, const float* __restrict__ item_diff,
    const float* __restrict__ item_disc, const float* __restrict__ q_table)
{
    extern __shared__ float ps[];
    float* s0 = ps;            // [128][33]
    float* s1 = ps + 4224;
    float* s2 = ps + 8448;
    __shared__ int su[32], sq[32];

    const int tid = threadIdx.x;
    const int b0 = blockIdx.x * 32;
    const int E = ep.E;

    if (tid < 32) {
        su[tid] = user_id[b0 + tid];
        sq[tid] = question_id[b0 + tid];
        g_disc[b0 + tid] = sigmoidf(item_disc[sq[tid]]);
    }
    __syncthreads();

    // ---- phase 1: bp / (diff*q) / q, staged transposed ----
    {
        const int r = tid >> 7;          // 0/1
        const int c = tid & 127;
        #pragma unroll 4
        for (int i = 0; i < 16; i++) {
            const int bl = i * 2 + r;
            const int u = su[bl];
            const int q = sq[bl];
            s0[c * 33 + bl] = sigmoidf(priori[(size_t)u * NUM_CONCEPT + c]);
            float qv = q_table[(size_t)q * NUM_CONCEPT + c];
            s1[c * 33 + bl] = sigmoidf(item_diff[(size_t)q * NUM_CONCEPT + c]) * qv;
            s2[c * 33 + bl] = qv;
        }
    }
    __syncthreads();
    {
        const int k = tid >> 5;          // 8 rows per pass
        const int bl = tid & 31;
        #pragma unroll 4
        for (int i = 0; i < 16; i++) {
            const int kk = i * 8 + k;
            g_bpT[(size_t)kk * BATCH + b0 + bl] = s0[kk * 33 + bl];
            g_AiT[(size_t)kk * BATCH + b0 + bl] = s1[kk * 33 + bl];
            g_qT[(size_t)kk * BATCH + b0 + bl]  = s2[kk * 33 + bl];
        }
    }

    // ---- phase 2: cp / cn in edge chunks of 128, staged transposed ----
    for (int e0 = 0; e0 < E; e0 += 128) {
        __syncthreads();
        {
            const int r = tid >> 7;
            const int c = tid & 127;
            const int e = e0 + c;
            if (e < E) {
                const float iv = ep.invl[e];
                #pragma unroll 4
                for (int i = 0; i < 16; i++) {
                    const int bl = i * 2 + r;
                    const int u = su[bl];
                    float p = sigmoidf(condi_p[(size_t)u * E + e]);
                    float n = sigmoidf(condi_n[(size_t)u * E + e]);
                    if (iv == 0.5f) { p = sqrtf(p); n = sqrtf(n); }
                    else if (iv != 1.0f) {
                        p = __powf(p, iv);
                        n = __powf(n, iv);
                    }
                    s0[c * 33 + bl] = p;
                    s1[c * 33 + bl] = n;
                }
            }
        }
        __syncthreads();
        {
            const int k = tid >> 5;
            const int bl = tid & 31;
            #pragma unroll 4
            for (int i = 0; i < 16; i++) {
                const int e = e0 + i * 8 + k;
                if (e < E) {
                    g_cpT[(size_t)e * BATCH + b0 + bl] = s0[(i * 8 + k) * 33 + bl];
                    g_cnT[(size_t)e * BATCH + b0 + bl] = s1[(i * 8 + k) * 33 + bl];
                }
            }
        }
    }
}

// ---------------- kernel B: sequential DAG (coalesced float2) ---------------
// 64 threads per block, each thread handles 2 adjacent batch elements.
__global__ __launch_bounds__(64) void dag_kernel(Graph g)
{
    extern __shared__ float2 post[];   // [128][64]
    const int tid = threadIdx.x;
    const int b = blockIdx.x * 128 + tid * 2;

    for (int k = 0; k < NUM_CONCEPT; k++) {
        const int l = g.lp[k];
        float2 pk;
        if (l == 0) {
            pk = *(const float2*)&g_bpT[(size_t)k * BATCH + b];
        } else {
            const int o = g.off[k];
            pk = make_float2(1.0f, 1.0f);
            #pragma unroll 3
            for (int j = 0; j < 3; j++) {
                if (j >= l) break;
                float2 pr = post[(int)g.pred[k][j] * 64 + tid];
                float2 cp = *(const float2*)&g_cpT[(size_t)(o + j) * BATCH + b];
                float2 cn = *(const float2*)&g_cnT[(size_t)(o + j) * BATCH + b];
                pk.x *= cn.x + pr.x * (cp.x - cn.x);
                pk.y *= cn.y + pr.y * (cp.y - cn.y);
            }
        }
        post[k * 64 + tid] = pk;
        float2 q = *(const float2*)&g_qT[(size_t)k * BATCH + b];
        float2 au = make_float2(pk.x * q.x, pk.y * q.y);
        *(float2*)&g_AuT[(size_t)k * BATCH + b] = au;
    }
}

// ---------------- kernel C: dual tf32 GEMM layer 1 + fused epilogue ---------
__global__ __launch_bounds__(256, 1) void gemm_layer1(
    const float* __restrict__ Wu, const float* __restrict__ Wi,
    const float* __restrict__ bu, const float* __restrict__ bi)
{
    extern __shared__ float smem[];
    float* sAu = smem;                 // [64][132]
    float* sAi = smem + 8448;          // [64][132]
    float* sWu = smem + 16896;         // [64][68]
    float* sWi = smem + 16896 + 4352;  // [64][68]

    const int tid = threadIdx.x;
    const int lane = tid & 31;
    const int wid = tid >> 5;
    const int wm = wid & 3;
    const int wn = wid >> 2;
    const int r = lane >> 2;
    const int cq = lane & 3;
    const int m0 = blockIdx.x * 128;
    const int n0 = blockIdx.y * 64;

    float accU[2][4][4], accI[2][4][4];
    #pragma unroll
    for (int mi = 0; mi < 2; mi++)
        #pragma unroll
        for (int ni = 0; ni < 4; ni++)
            #pragma unroll
            for (int t = 0; t < 4; t++) { accU[mi][ni][t] = 0.f; accI[mi][ni][t] = 0.f; }

    for (int kc = 0; kc < 2; kc++) {
        #pragma unroll
        for (int f0 = 0; f0 < 2048; f0 += 256) {
            int f = f0 + tid;
            int k = f >> 5, mq = f & 31;
            float4 v = *(const float4*)&g_AuT[(size_t)(kc * 64 + k) * BATCH + m0 + mq * 4];
            v.x = to_tf32(v.x); v.y = to_tf32(v.y); v.z = to_tf32(v.z); v.w = to_tf32(v.w);
            *(float4*)&sAu[k * 132 + mq * 4] = v;
            float4 w = *(const float4*)&g_AiT[(size_t)(kc * 64 + k) * BATCH + m0 + mq * 4];
            w.x = to_tf32(w.x); w.y = to_tf32(w.y); w.z = to_tf32(w.z); w.w = to_tf32(w.w);
            *(float4*)&sAi[k * 132 + mq * 4] = w;
        }
        #pragma unroll
        for (int f0 = 0; f0 < 1024; f0 += 256) {
            int f = f0 + tid;
            int n = f >> 4, kq = f & 15;
            float4 v = *(const float4*)&Wu[(size_t)(n0 + n) * NUM_CONCEPT + kc * 64 + kq * 4];
            v.x = to_tf32(v.x); v.y = to_tf32(v.y); v.z = to_tf32(v.z); v.w = to_tf32(v.w);
            *(float4*)&sWu[n * 68 + kq * 4] = v;
            float4 w = *(const float4*)&Wi[(size_t)(n0 + n) * NUM_CONCEPT + kc * 64 + kq * 4];
            w.x = to_tf32(w.x); w.y = to_tf32(w.y); w.z = to_tf32(w.z); w.w = to_tf32(w.w);
            *(float4*)&sWi[n * 68 + kq * 4] = w;
        }
        __syncthreads();

        #pragma unroll
        for (int kk = 0; kk < 64; kk += 8) {
            unsigned aU[2][4], aI[2][4], bU[4][2], bI[4][2];
            #pragma unroll
            for (int mi = 0; mi < 2; mi++) {
                int m = wm * 32 + mi * 16 + r;
                const float* p0 = &sAu[(kk + cq) * 132 + m];
                const float* p1 = &sAu[(kk + 4 + cq) * 132 + m];
                aU[mi][0] = __float_as_uint(p0[0]);
                aU[mi][1] = __float_as_uint(p0[8]);
                aU[mi][2] = __float_as_uint(p1[0]);
                aU[mi][3] = __float_as_uint(p1[8]);
                const float* q0 = &sAi[(kk + cq) * 132 + m];
                const float* q1 = &sAi[(kk + 4 + cq) * 132 + m];
                aI[mi][0] = __float_as_uint(q0[0]);
                aI[mi][1] = __float_as_uint(q0[8]);
                aI[mi][2] = __float_as_uint(q1[0]);
                aI[mi][3] = __float_as_uint(q1[8]);
            }
            #pragma unroll
            for (int ni = 0; ni < 4; ni++) {
                int n = wn * 32 + ni * 8 + r;
                bU[ni][0] = __float_as_uint(sWu[n * 68 + kk + cq]);
                bU[ni][1] = __float_as_uint(sWu[n * 68 + kk + 4 + cq]);
                bI[ni][0] = __float_as_uint(sWi[n * 68 + kk + cq]);
                bI[ni][1] = __float_as_uint(sWi[n * 68 + kk + 4 + cq]);
            }
            #pragma unroll
            for (int mi = 0; mi < 2; mi++)
                #pragma unroll
                for (int ni = 0; ni < 4; ni++) {
                    mma_tf32(accU[mi][ni], aU[mi], bU[ni]);
                    mma_tf32(accI[mi][ni], aI[mi], bI[ni]);
                }
        }
        __syncthreads();
    }

    float* sX = smem;  // [64][132] n x m
    #pragma unroll
    for (int mi = 0; mi < 2; mi++) {
        int ml0 = wm * 32 + mi * 16 + r;
        int ml1 = ml0 + 8;
        float d0 = g_disc[m0 + ml0];
        float d1 = g_disc[m0 + ml1];
        #pragma unroll
        for (int ni = 0; ni < 4; ni++) {
            int nl0 = wn * 32 + ni * 8 + 2 * cq;
            int nl1 = nl0 + 1;
            float bu0 = bu[n0 + nl0], bu1 = bu[n0 + nl1];
            float bi0 = bi[n0 + nl0], bi1 = bi[n0 + nl1];
            float* aU = accU[mi][ni];
            float* aI = accI[mi][ni];
            sX[nl0 * 132 + ml0] = (tanhf(aU[0] + bu0) - sigmoidf(aI[0] + bi0)) * d0;
            sX[nl1 * 132 + ml0] = (tanhf(aU[1] + bu1) - sigmoidf(aI[1] + bi1)) * d0;
            sX[nl0 * 132 + ml1] = (tanhf(aU[2] + bu0) - sigmoidf(aI[2] + bi0)) * d1;
            sX[nl1 * 132 + ml1] = (tanhf(aU[3] + bu1) - sigmoidf(aI[3] + bi1)) * d1;
        }
    }
    __syncthreads();
    #pragma unroll
    for (int f0 = 0; f0 < 2048; f0 += 256) {
        int f = f0 + tid;
        int nl = f >> 5, mq = f & 31;
        *(float4*)&g_XT[(size_t)(n0 + nl) * BATCH + m0 + mq * 4] =
            *(const float4*)&sX[nl * 132 + mq * 4];
    }
}

// ---------------- kernel D: tf32 GEMM layer 2 (K=512 -> N=256) + sigmoid ----
__global__ __launch_bounds__(256, 1) void gemm_layer2(
    const float* __restrict__ W1, const float* __restrict__ b1)
{
    extern __shared__ float smem[];
    float* sA = smem;            // [64][132]
    float* sW = smem + 8448;     // [64][68]

    const int tid = threadIdx.x;
    const int lane = tid & 31;
    const int wid = tid >> 5;
    const int wm = wid & 3;
    const int wn = wid >> 2;
    const int r = lane >> 2;
    const int cq = lane & 3;
    const int m0 = blockIdx.x * 128;
    const int n0 = blockIdx.y * 64;

    float acc[2][4][4];
    #pragma unroll
    for (int mi = 0; mi < 2; mi++)
        #pragma unroll
        for (int ni = 0; ni < 4; ni++)
            #pragma unroll
            for (int t = 0; t < 4; t++) acc[mi][ni][t] = 0.f;

    for (int kc = 0; kc < 8; kc++) {
        #pragma unroll
        for (int f0 = 0; f0 < 2048; f0 += 256) {
            int f = f0 + tid;
            int k = f >> 5, mq = f & 31;
            float4 v = *(const float4*)&g_XT[(size_t)(kc * 64 + k) * BATCH + m0 + mq * 4];
            v.x = to_tf32(v.x); v.y = to_tf32(v.y); v.z = to_tf32(v.z); v.w = to_tf32(v.w);
            *(float4*)&sA[k * 132 + mq * 4] = v;
        }
        #pragma unroll
        for (int f0 = 0; f0 < 1024; f0 += 256) {
            int f = f0 + tid;
            int n = f >> 4, kq = f & 15;
            float4 v = *(const float4*)&W1[(size_t)(n0 + n) * DIM_HIDDEN + kc * 64 + kq * 4];
            v.x = to_tf32(v.x); v.y = to_tf32(v.y); v.z = to_tf32(v.z); v.w = to_tf32(v.w);
            *(float4*)&sW[n * 68 + kq * 4] = v;
        }
        __syncthreads();

        #pragma unroll
        for (int kk = 0; kk < 64; kk += 8) {
            unsigned a[2][4], b[4][2];
            #pragma unroll
            for (int mi = 0; mi < 2; mi++) {
                int m = wm * 32 + mi * 16 + r;
                const float* p0 = &sA[(kk + cq) * 132 + m];
                const float* p1 = &sA[(kk + 4 + cq) * 132 + m];
                a[mi][0] = __float_as_uint(p0[0]);
                a[mi][1] = __float_as_uint(p0[8]);
                a[mi][2] = __float_as_uint(p1[0]);
                a[mi][3] = __float_as_uint(p1[8]);
            }
            #pragma unroll
            for (int ni = 0; ni < 4; ni++) {
                int n = wn * 32 + ni * 8 + r;
                b[ni][0] = __float_as_uint(sW[n * 68 + kk + cq]);
                b[ni][1] = __float_as_uint(sW[n * 68 + kk + 4 + cq]);
            }
            #pragma unroll
            for (int mi = 0; mi < 2; mi++)
                #pragma unroll
                for (int ni = 0; ni < 4; ni++)
                    mma_tf32(acc[mi][ni], a[mi], b[ni]);
        }
        __syncthreads();
    }

    #pragma unroll
    for (int mi = 0; mi < 2; mi++) {
        int mg0 = m0 + wm * 32 + mi * 16 + r;
        int mg1 = mg0 + 8;
        #pragma unroll
        for (int ni = 0; ni < 4; ni++) {
            int ng = n0 + wn * 32 + ni * 8 + 2 * cq;
            float b0 = b1[ng], b1v = b1[ng + 1];
            float* a = acc[mi][ni];
            float2 v0 = make_float2(sigmoidf(a[0] + b0), sigmoidf(a[1] + b1v));
            float2 v1 = make_float2(sigmoidf(a[2] + b0), sigmoidf(a[3] + b1v));
            *(float2*)&g_H[(size_t)mg0 * H2 + ng] = v0;
            *(float2*)&g_H[(size_t)mg1 * H2 + ng] = v1;
        }
    }
}

// ---------------- kernel E: final matvec (256 -> 1) + sigmoid ---------------
__global__ __launch_bounds__(256) void final_kernel(
    const float* __restrict__ W2, const float* __restrict__ b2,
    float* __restrict__ out)
{
    __shared__ float w[H2];
    const int tid = threadIdx.x;
    const int lane = tid & 31;
    const int wid = tid >> 5;
    w[tid] = W2[tid];
    __syncthreads();
    const int m = blockIdx.x * 8 + wid;
    const float4* hp = (const float4*)(g_H + (size_t)m * H2);
    float s = 0.f;
    #pragma unroll
    for (int i = 0; i < 2; i++) {
        int idx = lane * 2 + i;
        float4 v = hp[idx];
        int k = idx * 4;
        s += v.x * w[k] + v.y * w[k + 1] + v.z * w[k + 2] + v.w * w[k + 3];
    }
    #pragma unroll
    for (int off = 16; off > 0; off >>= 1)
        s += __shfl_xor_sync(0xffffffffu, s, off);
    if (lane == 0) out[m] = sigmoidf(s + b2[0]);
}

// ---------------- launch -----------------------------------------------------
extern "C" void kernel_launch(void* const* d_in, const int* in_sizes, int n_in,
                              void* d_out, int out_size)
{
    Graph g;
    EdgeParams ep;
    build_graph(g, ep);

    const int*   user_id     = (const int*)d_in[0];
    const int*   question_id = (const int*)d_in[1];
    const float* priori      = (const float*)d_in[2];
    const float* condi_p     = (const float*)d_in[3];
    const float* condi_n     = (const float*)d_in[4];
    const float* item_diff   = (const float*)d_in[5];
    const float* item_disc   = (const float*)d_in[6];
    const float* q_table     = (const float*)d_in[7];
    const float* Wu          = (const float*)d_in[8];
    const float* bu          = (const float*)d_in[9];
    const float* Wi          = (const float*)d_in[10];
    const float* bi          = (const float*)d_in[11];
    const float* W1          = (const float*)d_in[12];
    const float* b1          = (const float*)d_in[13];
    const float* W2          = (const float*)d_in[14];
    const float* b2          = (const float*)d_in[15];
    float* out = (float*)d_out;

    ep.E = g.E;

    cudaFuncSetAttribute(precompute_kernel, cudaFuncAttributeMaxDynamicSharedMemorySize, 50688);
    cudaFuncSetAttribute(dag_kernel, cudaFuncAttributeMaxDynamicSharedMemorySize, 65536);
    cudaFuncSetAttribute(gemm_layer1, cudaFuncAttributeMaxDynamicSharedMemorySize, 102400);
    cudaFuncSetAttribute(gemm_layer2, cudaFuncAttributeMaxDynamicSharedMemorySize, 51200);

    precompute_kernel<<<BATCH / 32, 256, 50688>>>(ep, user_id, question_id, priori,
                                                  condi_p, condi_n, item_diff,
                                                  item_disc, q_table);

    dag_kernel<<<BATCH / 128, 64, 65536>>>(g);

    dim3 grid1(BATCH / 128, DIM_HIDDEN / 64);
    gemm_layer1<<<grid1, 256, 102400>>>(Wu, Wi, bu, bi);

    dim3 grid2(BATCH / 128, H2 / 64);
    gemm_layer2<<<grid2, 256, 51200>>>(W1, b1);

    final_kernel<<<BATCH / 8, 256>>>(W2, b2, out);
}

// round 4
// speedup vs baseline: 1.0372x; 1.0372x over previous
#include <cuda_runtime.h>
#include <cuda_bf16.h>
#include <cstdint>

#define NUM_USER 200000
#define NUM_QUESTION 20000
#define NUM_CONCEPT 128
#define DIM_HIDDEN 512
#define H2 256
#define BATCH 16384
#define EMAX 400
#define PSLOTS (NUM_CONCEPT * 3)   // padded edge slots

// ---------------- scratch (device globals; no allocations allowed) ----------
__device__ float g_baseT[NUM_CONCEPT * BATCH];   // roots: sigmoid(priori); else 1
__device__ float g_cpP[PSLOTS * BATCH];          // padded cp^(1/l), feature-major
__device__ float g_cnP[PSLOTS * BATCH];          // padded cn^(1/l)
__device__ float g_qT[NUM_CONCEPT * BATCH];      // q gathered, feature-major [k][b]
__device__ float g_AuT[NUM_CONCEPT * BATCH];     // post*q, feature-major
__device__ float g_AiT[NUM_CONCEPT * BATCH];     // sigmoid(diff)*q, feature-major
__device__ float g_disc[BATCH];
__device__ float g_XT[DIM_HIDDEN * BATCH];       // layer-1 output, feature-major
__device__ float g_H[BATCH * H2];                // layer-2 output, row-major

// ---------------- graph structure (replicated numpy RandomState(0)) ---------
struct Graph {
    int E;
    unsigned char lp[NUM_CONCEPT];
    short off[NUM_CONCEPT];
    unsigned char pred[NUM_CONCEPT][3];
};
// padded schedule for precompute
struct Sched {
    short src[PSLOTS];          // original edge index or -1 (dummy)
    float invl[PSLOTS];         // 1, 0.5, or 1/3
    unsigned char is_root[NUM_CONCEPT];
};
// padded preds for dag
struct DagG {
    unsigned char pred[NUM_CONCEPT][3];
};

struct MT19937 {
    uint32_t mt[624];
    int mti;
    void seed(uint32_t s) {
        mt[0] = s;
        for (int i = 1; i < 624; i++)
            mt[i] = 1812433253u * (mt[i - 1] ^ (mt[i - 1] >> 30)) + (uint32_t)i;
        mti = 624;
    }
    uint32_t next() {
        if (mti >= 624) {
            for (int i = 0; i < 624; i++) {
                uint32_t y = (mt[i] & 0x80000000u) | (mt[(i + 1) % 624] & 0x7fffffffu);
                uint32_t v = mt[(i + 397) % 624] ^ (y >> 1);
                if (y & 1u) v ^= 0x9908b0dfu;
                mt[i] = v;
            }
            mti = 0;
        }
        uint32_t y = mt[mti++];
        y ^= y >> 11;
        y ^= (y << 7) & 0x9d2c5680u;
        y ^= (y << 15) & 0xefc60000u;
        y ^= y >> 18;
        return y;
    }
    uint32_t interval(uint32_t mx) {
        if (mx == 0) return 0;
        uint32_t mask = mx;
        mask |= mask >> 1; mask |= mask >> 2; mask |= mask >> 4;
        mask |= mask >> 8; mask |= mask >> 16;
        uint32_t v;
        do { v = next() & mask; } while (v > mx);
        return v;
    }
};

static void build_graph(Graph& g, Sched& sc, DagG& dg) {
    MT19937 r;
    r.seed(0u);
    int E = 0;
    for (int k = 0; k < NUM_CONCEPT; k++) {
        int l = 0;
        if (k > 0) {
            int hi = (k < 3) ? k : 3;
            l = (int)r.interval((uint32_t)hi);
        }
        g.lp[k] = (unsigned char)l;
        g.off[k] = (short)E;
        g.pred[k][0] = g.pred[k][1] = g.pred[k][2] = 0;
        sc.is_root[k] = (l == 0) ? 1 : 0;
        if (l > 0) {
            int perm[NUM_CONCEPT];
            for (int i = 0; i < k; i++) perm[i] = i;
            for (int i = k - 1; i >= 1; i--) {
                int j = (int)r.interval((uint32_t)i);
                int t = perm[i]; perm[i] = perm[j]; perm[j] = t;
            }
            int p[3];
            for (int j = 0; j < l; j++) p[j] = perm[j];
            for (int a = 0; a < l; a++)
                for (int b = a + 1; b < l; b++)
                    if (p[b] < p[a]) { int t = p[a]; p[a] = p[b]; p[b] = t; }
            for (int j = 0; j < l; j++) g.pred[k][j] = (unsigned char)p[j];
        }
        // padded slots
        for (int j = 0; j < 3; j++) {
            int s = k * 3 + j;
            if (j < l) {
                sc.src[s] = (short)(E + j);
                sc.invl[s] = 1.0f / (float)l;
                dg.pred[k][j] = g.pred[k][j];
            } else {
                sc.src[s] = -1;
                sc.invl[s] = 1.0f;
                dg.pred[k][j] = 0;
            }
        }
        E += l;
    }
    g.E = E;
}

// ---------------- device helpers --------------------------------------------
__device__ __forceinline__ float sigmoidf(float x) {
    return 1.0f / (1.0f + __expf(-x));
}
__device__ __forceinline__ float to_tf32(float x) {
    unsigned u;
    asm("cvt.rna.tf32.f32 %0, %1;" : "=r"(u) : "f"(x));
    return __uint_as_float(u);
}
__device__ __forceinline__ void mma_tf32(float* c, const unsigned* a, const unsigned* b) {
    asm volatile(
        "mma.sync.aligned.m16n8k8.row.col.f32.tf32.tf32.f32 "
        "{%0,%1,%2,%3}, {%4,%5,%6,%7}, {%8,%9}, {%0,%1,%2,%3};\n"
        : "+f"(c[0]), "+f"(c[1]), "+f"(c[2]), "+f"(c[3])
        : "r"(a[0]), "r"(a[1]), "r"(a[2]), "r"(a[3]), "r"(b[0]), "r"(b[1]));
}

// ---------------- kernel A: elementwise precompute + transposes -------------
// Block handles 32 batch elements; 256 threads. Outputs feature-major, padded.
__global__ __launch_bounds__(256) void precompute_kernel(
    Sched sc, int E,
    const int* __restrict__ user_id, const int* __restrict__ question_id,
    const float* __restrict__ priori, const float* __restrict__ condi_p,
    const float* __restrict__ condi_n, const float* __restrict__ item_diff,
    const float* __restrict__ item_disc, const float* __restrict__ q_table)
{
    extern __shared__ float ps[];
    float* s0 = ps;            // [128][33]
    float* s1 = ps + 4224;
    float* s2 = ps + 8448;
    __shared__ int su[32], sq[32];

    const int tid = threadIdx.x;
    const int b0 = blockIdx.x * 32;

    if (tid < 32) {
        su[tid] = user_id[b0 + tid];
        sq[tid] = question_id[b0 + tid];
        g_disc[b0 + tid] = sigmoidf(item_disc[sq[tid]]);
    }
    __syncthreads();

    // ---- phase 1: base / (diff*q) / q, staged transposed ----
    {
        const int r = tid >> 7;          // 0/1
        const int c = tid & 127;
        const bool root = sc.is_root[c] != 0;
        #pragma unroll 4
        for (int i = 0; i < 16; i++) {
            const int bl = i * 2 + r;
            const int u = su[bl];
            const int q = sq[bl];
            float bv = 1.0f;
            if (root) bv = sigmoidf(priori[(size_t)u * NUM_CONCEPT + c]);
            s0[c * 33 + bl] = bv;
            float qv = q_table[(size_t)q * NUM_CONCEPT + c];
            s1[c * 33 + bl] = sigmoidf(item_diff[(size_t)q * NUM_CONCEPT + c]) * qv;
            s2[c * 33 + bl] = qv;
        }
    }
    __syncthreads();
    {
        const int k = tid >> 5;          // 8 rows per pass
        const int bl = tid & 31;
        #pragma unroll 4
        for (int i = 0; i < 16; i++) {
            const int kk = i * 8 + k;
            g_baseT[(size_t)kk * BATCH + b0 + bl] = s0[kk * 33 + bl];
            g_AiT[(size_t)kk * BATCH + b0 + bl]  = s1[kk * 33 + bl];
            g_qT[(size_t)kk * BATCH + b0 + bl]   = s2[kk * 33 + bl];
        }
    }

    // ---- phase 2: padded cp/cn in 3 chunks of 128 slots, staged transposed --
    for (int cidx = 0; cidx < 3; cidx++) {
        __syncthreads();
        {
            const int r = tid >> 7;
            const int c = tid & 127;
            const int s = cidx * 128 + c;
            const int src = sc.src[s];
            const float iv = sc.invl[s];
            #pragma unroll 4
            for (int i = 0; i < 16; i++) {
                const int bl = i * 2 + r;
                const int u = su[bl];
                float p = 1.0f, n = 1.0f;
                if (src >= 0) {
                    p = sigmoidf(condi_p[(size_t)u * E + src]);
                    n = sigmoidf(condi_n[(size_t)u * E + src]);
                    if (iv == 0.5f) { p = sqrtf(p); n = sqrtf(n); }
                    else if (iv != 1.0f) {
                        p = __powf(p, iv);
                        n = __powf(n, iv);
                    }
                }
                s0[c * 33 + bl] = p;
                s1[c * 33 + bl] = n;
            }
        }
        __syncthreads();
        {
            const int k = tid >> 5;
            const int bl = tid & 31;
            #pragma unroll 4
            for (int i = 0; i < 16; i++) {
                const int s = cidx * 128 + i * 8 + k;
                g_cpP[(size_t)s * BATCH + b0 + bl] = s0[(i * 8 + k) * 33 + bl];
                g_cnP[(size_t)s * BATCH + b0 + bl] = s1[(i * 8 + k) * 33 + bl];
            }
        }
    }
}

// ---------------- kernel B: branchless DAG, fully pipelined -----------------
// 64 threads/block, 1 element each; thread-private smem column -> no syncs.
__global__ __launch_bounds__(64) void dag_kernel(DagG dg)
{
    __shared__ float post[NUM_CONCEPT * 64];
    const int tid = threadIdx.x;
    const int b = blockIdx.x * 64 + tid;

    post[tid] = 0.0f;     // k=0 column slot: dummy preds read this safely

    #pragma unroll 8
    for (int k = 0; k < NUM_CONCEPT; k++) {
        float pk = g_baseT[(size_t)k * BATCH + b];
        #pragma unroll
        for (int j = 0; j < 3; j++) {
            float pr = post[(int)dg.pred[k][j] * 64 + tid];
            float cp = g_cpP[(size_t)(k * 3 + j) * BATCH + b];
            float cn = g_cnP[(size_t)(k * 3 + j) * BATCH + b];
            pk *= cn + pr * (cp - cn);
        }
        post[k * 64 + tid] = pk;
        g_AuT[(size_t)k * BATCH + b] = pk * g_qT[(size_t)k * BATCH + b];
    }
}

// ---------------- kernel C: dual tf32 GEMM layer 1 + fused epilogue ---------
__global__ __launch_bounds__(256, 1) void gemm_layer1(
    const float* __restrict__ Wu, const float* __restrict__ Wi,
    const float* __restrict__ bu, const float* __restrict__ bi)
{
    extern __shared__ float smem[];
    float* sAu = smem;                 // [64][132]
    float* sAi = smem + 8448;          // [64][132]
    float* sWu = smem + 16896;         // [64][68]
    float* sWi = smem + 16896 + 4352;  // [64][68]

    const int tid = threadIdx.x;
    const int lane = tid & 31;
    const int wid = tid >> 5;
    const int wm = wid & 3;
    const int wn = wid >> 2;
    const int r = lane >> 2;
    const int cq = lane & 3;
    const int m0 = blockIdx.x * 128;
    const int n0 = blockIdx.y * 64;

    float accU[2][4][4], accI[2][4][4];
    #pragma unroll
    for (int mi = 0; mi < 2; mi++)
        #pragma unroll
        for (int ni = 0; ni < 4; ni++)
            #pragma unroll
            for (int t = 0; t < 4; t++) { accU[mi][ni][t] = 0.f; accI[mi][ni][t] = 0.f; }

    for (int kc = 0; kc < 2; kc++) {
        #pragma unroll
        for (int f0 = 0; f0 < 2048; f0 += 256) {
            int f = f0 + tid;
            int k = f >> 5, mq = f & 31;
            float4 v = *(const float4*)&g_AuT[(size_t)(kc * 64 + k) * BATCH + m0 + mq * 4];
            v.x = to_tf32(v.x); v.y = to_tf32(v.y); v.z = to_tf32(v.z); v.w = to_tf32(v.w);
            *(float4*)&sAu[k * 132 + mq * 4] = v;
            float4 w = *(const float4*)&g_AiT[(size_t)(kc * 64 + k) * BATCH + m0 + mq * 4];
            w.x = to_tf32(w.x); w.y = to_tf32(w.y); w.z = to_tf32(w.z); w.w = to_tf32(w.w);
            *(float4*)&sAi[k * 132 + mq * 4] = w;
        }
        #pragma unroll
        for (int f0 = 0; f0 < 1024; f0 += 256) {
            int f = f0 + tid;
            int n = f >> 4, kq = f & 15;
            float4 v = *(const float4*)&Wu[(size_t)(n0 + n) * NUM_CONCEPT + kc * 64 + kq * 4];
            v.x = to_tf32(v.x); v.y = to_tf32(v.y); v.z = to_tf32(v.z); v.w = to_tf32(v.w);
            *(float4*)&sWu[n * 68 + kq * 4] = v;
            float4 w = *(const float4*)&Wi[(size_t)(n0 + n) * NUM_CONCEPT + kc * 64 + kq * 4];
            w.x = to_tf32(w.x); w.y = to_tf32(w.y); w.z = to_tf32(w.z); w.w = to_tf32(w.w);
            *(float4*)&sWi[n * 68 + kq * 4] = w;
        }
        __syncthreads();

        #pragma unroll
        for (int kk = 0; kk < 64; kk += 8) {
            unsigned aU[2][4], aI[2][4], bU[4][2], bI[4][2];
            #pragma unroll
            for (int mi = 0; mi < 2; mi++) {
                int m = wm * 32 + mi * 16 + r;
                const float* p0 = &sAu[(kk + cq) * 132 + m];
                const float* p1 = &sAu[(kk + 4 + cq) * 132 + m];
                aU[mi][0] = __float_as_uint(p0[0]);
                aU[mi][1] = __float_as_uint(p0[8]);
                aU[mi][2] = __float_as_uint(p1[0]);
                aU[mi][3] = __float_as_uint(p1[8]);
                const float* q0 = &sAi[(kk + cq) * 132 + m];
                const float* q1 = &sAi[(kk + 4 + cq) * 132 + m];
                aI[mi][0] = __float_as_uint(q0[0]);
                aI[mi][1] = __float_as_uint(q0[8]);
                aI[mi][2] = __float_as_uint(q1[0]);
                aI[mi][3] = __float_as_uint(q1[8]);
            }
            #pragma unroll
            for (int ni = 0; ni < 4; ni++) {
                int n = wn * 32 + ni * 8 + r;
                bU[ni][0] = __float_as_uint(sWu[n * 68 + kk + cq]);
                bU[ni][1] = __float_as_uint(sWu[n * 68 + kk + 4 + cq]);
                bI[ni][0] = __float_as_uint(sWi[n * 68 + kk + cq]);
                bI[ni][1] = __float_as_uint(sWi[n * 68 + kk + 4 + cq]);
            }
            #pragma unroll
            for (int mi = 0; mi < 2; mi++)
                #pragma unroll
                for (int ni = 0; ni < 4; ni++) {
                    mma_tf32(accU[mi][ni], aU[mi], bU[ni]);
                    mma_tf32(accI[mi][ni], aI[mi], bI[ni]);
                }
        }
        __syncthreads();
    }

    float* sX = smem;  // [64][132] n x m
    #pragma unroll
    for (int mi = 0; mi < 2; mi++) {
        int ml0 = wm * 32 + mi * 16 + r;
        int ml1 = ml0 + 8;
        float d0 = g_disc[m0 + ml0];
        float d1 = g_disc[m0 + ml1];
        #pragma unroll
        for (int ni = 0; ni < 4; ni++) {
            int nl0 = wn * 32 + ni * 8 + 2 * cq;
            int nl1 = nl0 + 1;
            float bu0 = bu[n0 + nl0], bu1 = bu[n0 + nl1];
            float bi0 = bi[n0 + nl0], bi1 = bi[n0 + nl1];
            float* aU = accU[mi][ni];
            float* aI = accI[mi][ni];
            sX[nl0 * 132 + ml0] = (tanhf(aU[0] + bu0) - sigmoidf(aI[0] + bi0)) * d0;
            sX[nl1 * 132 + ml0] = (tanhf(aU[1] + bu1) - sigmoidf(aI[1] + bi1)) * d0;
            sX[nl0 * 132 + ml1] = (tanhf(aU[2] + bu0) - sigmoidf(aI[2] + bi0)) * d1;
            sX[nl1 * 132 + ml1] = (tanhf(aU[3] + bu1) - sigmoidf(aI[3] + bi1)) * d1;
        }
    }
    __syncthreads();
    #pragma unroll
    for (int f0 = 0; f0 < 2048; f0 += 256) {
        int f = f0 + tid;
        int nl = f >> 5, mq = f & 31;
        *(float4*)&g_XT[(size_t)(n0 + nl) * BATCH + m0 + mq * 4] =
            *(const float4*)&sX[nl * 132 + mq * 4];
    }
}

// ---------------- kernel D: tf32 GEMM layer 2 (K=512 -> N=256) + sigmoid ----
__global__ __launch_bounds__(256, 1) void gemm_layer2(
    const float* __restrict__ W1, const float* __restrict__ b1)
{
    extern __shared__ float smem[];
    float* sA = smem;            // [64][132]
    float* sW = smem + 8448;     // [64][68]

    const int tid = threadIdx.x;
    const int lane = tid & 31;
    const int wid = tid >> 5;
    const int wm = wid & 3;
    const int wn = wid >> 2;
    const int r = lane >> 2;
    const int cq = lane & 3;
    const int m0 = blockIdx.x * 128;
    const int n0 = blockIdx.y * 64;

    float acc[2][4][4];
    #pragma unroll
    for (int mi = 0; mi < 2; mi++)
        #pragma unroll
        for (int ni = 0; ni < 4; ni++)
            #pragma unroll
            for (int t = 0; t < 4; t++) acc[mi][ni][t] = 0.f;

    for (int kc = 0; kc < 8; kc++) {
        #pragma unroll
        for (int f0 = 0; f0 < 2048; f0 += 256) {
            int f = f0 + tid;
            int k = f >> 5, mq = f & 31;
            float4 v = *(const float4*)&g_XT[(size_t)(kc * 64 + k) * BATCH + m0 + mq * 4];
            v.x = to_tf32(v.x); v.y = to_tf32(v.y); v.z = to_tf32(v.z); v.w = to_tf32(v.w);
            *(float4*)&sA[k * 132 + mq * 4] = v;
        }
        #pragma unroll
        for (int f0 = 0; f0 < 1024; f0 += 256) {
            int f = f0 + tid;
            int n = f >> 4, kq = f & 15;
            float4 v = *(const float4*)&W1[(size_t)(n0 + n) * DIM_HIDDEN + kc * 64 + kq * 4];
            v.x = to_tf32(v.x); v.y = to_tf32(v.y); v.z = to_tf32(v.z); v.w = to_tf32(v.w);
            *(float4*)&sW[n * 68 + kq * 4] = v;
        }
        __syncthreads();

        #pragma unroll
        for (int kk = 0; kk < 64; kk += 8) {
            unsigned a[2][4], b[4][2];
            #pragma unroll
            for (int mi = 0; mi < 2; mi++) {
                int m = wm * 32 + mi * 16 + r;
                const float* p0 = &sA[(kk + cq) * 132 + m];
                const float* p1 = &sA[(kk + 4 + cq) * 132 + m];
                a[mi][0] = __float_as_uint(p0[0]);
                a[mi][1] = __float_as_uint(p0[8]);
                a[mi][2] = __float_as_uint(p1[0]);
                a[mi][3] = __float_as_uint(p1[8]);
            }
            #pragma unroll
            for (int ni = 0; ni < 4; ni++) {
                int n = wn * 32 + ni * 8 + r;
                b[ni][0] = __float_as_uint(sW[n * 68 + kk + cq]);
                b[ni][1] = __float_as_uint(sW[n * 68 + kk + 4 + cq]);
            }
            #pragma unroll
            for (int mi = 0; mi < 2; mi++)
                #pragma unroll
                for (int ni = 0; ni < 4; ni++)
                    mma_tf32(acc[mi][ni], a[mi], b[ni]);
        }
        __syncthreads();
    }

    #pragma unroll
    for (int mi = 0; mi < 2; mi++) {
        int mg0 = m0 + wm * 32 + mi * 16 + r;
        int mg1 = mg0 + 8;
        #pragma unroll
        for (int ni = 0; ni < 4; ni++) {
            int ng = n0 + wn * 32 + ni * 8 + 2 * cq;
            float b0 = b1[ng], b1v = b1[ng + 1];
            float* a = acc[mi][ni];
            float2 v0 = make_float2(sigmoidf(a[0] + b0), sigmoidf(a[1] + b1v));
            float2 v1 = make_float2(sigmoidf(a[2] + b0), sigmoidf(a[3] + b1v));
            *(float2*)&g_H[(size_t)mg0 * H2 + ng] = v0;
            *(float2*)&g_H[(size_t)mg1 * H2 + ng] = v1;
        }
    }
}

// ---------------- kernel E: final matvec (256 -> 1) + sigmoid ---------------
__global__ __launch_bounds__(256) void final_kernel(
    const float* __restrict__ W2, const float* __restrict__ b2,
    float* __restrict__ out)
{
    __shared__ float w[H2];
    const int tid = threadIdx.x;
    const int lane = tid & 31;
    const int wid = tid >> 5;
    w[tid] = W2[tid];
    __syncthreads();
    const int m = blockIdx.x * 8 + wid;
    const float4* hp = (const float4*)(g_H + (size_t)m * H2);
    float s = 0.f;
    #pragma unroll
    for (int i = 0; i < 2; i++) {
        int idx = lane * 2 + i;
        float4 v = hp[idx];
        int k = idx * 4;
        s += v.x * w[k] + v.y * w[k + 1] + v.z * w[k + 2] + v.w * w[k + 3];
    }
    #pragma unroll
    for (int off = 16; off > 0; off >>= 1)
        s += __shfl_xor_sync(0xffffffffu, s, off);
    if (lane == 0) out[m] = sigmoidf(s + b2[0]);
}

// ---------------- launch -----------------------------------------------------
extern "C" void kernel_launch(void* const* d_in, const int* in_sizes, int n_in,
                              void* d_out, int out_size)
{
    Graph g;
    Sched sc;
    DagG dg;
    build_graph(g, sc, dg);

    const int*   user_id     = (const int*)d_in[0];
    const int*   question_id = (const int*)d_in[1];
    const float* priori      = (const float*)d_in[2];
    const float* condi_p     = (const float*)d_in[3];
    const float* condi_n     = (const float*)d_in[4];
    const float* item_diff   = (const float*)d_in[5];
    const float* item_disc   = (const float*)d_in[6];
    const float* q_table     = (const float*)d_in[7];
    const float* Wu          = (const float*)d_in[8];
    const float* bu          = (const float*)d_in[9];
    const float* Wi          = (const float*)d_in[10];
    const float* bi          = (const float*)d_in[11];
    const float* W1          = (const float*)d_in[12];
    const float* b1          = (const float*)d_in[13];
    const float* W2          = (const float*)d_in[14];
    const float* b2          = (const float*)d_in[15];
    float* out = (float*)d_out;

    const int E = in_sizes[3] / NUM_USER;

    cudaFuncSetAttribute(precompute_kernel, cudaFuncAttributeMaxDynamicSharedMemorySize, 50688);
    cudaFuncSetAttribute(gemm_layer1, cudaFuncAttributeMaxDynamicSharedMemorySize, 102400);
    cudaFuncSetAttribute(gemm_layer2, cudaFuncAttributeMaxDynamicSharedMemorySize, 51200);

    precompute_kernel<<<BATCH / 32, 256, 50688>>>(sc, E, user_id, question_id, priori,
                                                  condi_p, condi_n, item_diff,
                                                  item_disc, q_table);

    dag_kernel<<<BATCH / 64, 64>>>(dg);

    dim3 grid1(BATCH / 128, DIM_HIDDEN / 64);
    gemm_layer1<<<grid1, 256, 102400>>>(Wu, Wi, bu, bi);

    dim3 grid2(BATCH / 128, H2 / 64);
    gemm_layer2<<<grid2, 256, 51200>>>(W1, b1);

    final_kernel<<<BATCH / 8, 256>>>(W2, b2, out);
}

// round 5
// speedup vs baseline: 1.1621x; 1.1203x over previous
#include <cuda_runtime.h>
#include <cuda_bf16.h>
#include <cstdint>

#define NUM_USER 200000
#define NUM_QUESTION 20000
#define NUM_CONCEPT 128
#define DIM_HIDDEN 512
#define H2 256
#define BATCH 16384
#define EMAX 400
#define PSLOTS (NUM_CONCEPT * 3)

// ---------------- scratch (device globals; no allocations allowed) ----------
__device__ float g_baseT[NUM_CONCEPT * BATCH];
__device__ float g_cpP[PSLOTS * BATCH];
__device__ float g_cnP[PSLOTS * BATCH];
__device__ float g_qT[NUM_CONCEPT * BATCH];
__device__ float g_AuT[NUM_CONCEPT * BATCH];
__device__ float g_AiT[NUM_CONCEPT * BATCH];
__device__ float g_disc[BATCH];
__device__ float g_XT[DIM_HIDDEN * BATCH];
__device__ float g_H[BATCH * H2];

// ---------------- graph structure (replicated numpy RandomState(0)) ---------
struct Graph {
    int E;
    unsigned char lp[NUM_CONCEPT];
    short off[NUM_CONCEPT];
    unsigned char pred[NUM_CONCEPT][3];
};
struct Sched {
    short src[PSLOTS];
    float invl[PSLOTS];
    unsigned char is_root[NUM_CONCEPT];
};
struct DagG {
    unsigned char pred[NUM_CONCEPT][3];
};

struct MT19937 {
    uint32_t mt[624];
    int mti;
    void seed(uint32_t s) {
        mt[0] = s;
        for (int i = 1; i < 624; i++)
            mt[i] = 1812433253u * (mt[i - 1] ^ (mt[i - 1] >> 30)) + (uint32_t)i;
        mti = 624;
    }
    uint32_t next() {
        if (mti >= 624) {
            for (int i = 0; i < 624; i++) {
                uint32_t y = (mt[i] & 0x80000000u) | (mt[(i + 1) % 624] & 0x7fffffffu);
                uint32_t v = mt[(i + 397) % 624] ^ (y >> 1);
                if (y & 1u) v ^= 0x9908b0dfu;
                mt[i] = v;
            }
            mti = 0;
        }
        uint32_t y = mt[mti++];
        y ^= y >> 11;
        y ^= (y << 7) & 0x9d2c5680u;
        y ^= (y << 15) & 0xefc60000u;
        y ^= y >> 18;
        return y;
    }
    uint32_t interval(uint32_t mx) {
        if (mx == 0) return 0;
        uint32_t mask = mx;
        mask |= mask >> 1; mask |= mask >> 2; mask |= mask >> 4;
        mask |= mask >> 8; mask |= mask >> 16;
        uint32_t v;
        do { v = next() & mask; } while (v > mx);
        return v;
    }
};

static void build_graph(Graph& g, Sched& sc, DagG& dg) {
    MT19937 r;
    r.seed(0u);
    int E = 0;
    for (int k = 0; k < NUM_CONCEPT; k++) {
        int l = 0;
        if (k > 0) {
            int hi = (k < 3) ? k : 3;
            l = (int)r.interval((uint32_t)hi);
        }
        g.lp[k] = (unsigned char)l;
        g.off[k] = (short)E;
        g.pred[k][0] = g.pred[k][1] = g.pred[k][2] = 0;
        sc.is_root[k] = (l == 0) ? 1 : 0;
        if (l > 0) {
            int perm[NUM_CONCEPT];
            for (int i = 0; i < k; i++) perm[i] = i;
            for (int i = k - 1; i >= 1; i--) {
                int j = (int)r.interval((uint32_t)i);
                int t = perm[i]; perm[i] = perm[j]; perm[j] = t;
            }
            int p[3];
            for (int j = 0; j < l; j++) p[j] = perm[j];
            for (int a = 0; a < l; a++)
                for (int b = a + 1; b < l; b++)
                    if (p[b] < p[a]) { int t = p[a]; p[a] = p[b]; p[b] = t; }
            for (int j = 0; j < l; j++) g.pred[k][j] = (unsigned char)p[j];
        }
        for (int j = 0; j < 3; j++) {
            int s = k * 3 + j;
            if (j < l) {
                sc.src[s] = (short)(E + j);
                sc.invl[s] = 1.0f / (float)l;
                dg.pred[k][j] = g.pred[k][j];
            } else {
                sc.src[s] = -1;
                sc.invl[s] = 1.0f;
                dg.pred[k][j] = 0;
            }
        }
        E += l;
    }
    g.E = E;
}

// ---------------- device helpers --------------------------------------------
__device__ __forceinline__ float sigmoidf(float x) {
    return 1.0f / (1.0f + __expf(-x));
}
__device__ __forceinline__ void mma_tf32(float* c, const unsigned* a, const unsigned* b) {
    asm volatile(
        "mma.sync.aligned.m16n8k8.row.col.f32.tf32.tf32.f32 "
        "{%0,%1,%2,%3}, {%4,%5,%6,%7}, {%8,%9}, {%0,%1,%2,%3};\n"
        : "+f"(c[0]), "+f"(c[1]), "+f"(c[2]), "+f"(c[3])
        : "r"(a[0]), "r"(a[1]), "r"(a[2]), "r"(a[3]), "r"(b[0]), "r"(b[1]));
}
__device__ __forceinline__ void cpa16(float* dst_smem, const float* src) {
    unsigned a = (unsigned)__cvta_generic_to_shared(dst_smem);
    asm volatile("cp.async.ca.shared.global [%0], [%1], 16;" :: "r"(a), "l"(src));
}
#define CP_COMMIT() asm volatile("cp.async.commit_group;")
#define CP_WAIT0()  asm volatile("cp.async.wait_group 0;" ::: "memory")

// ---------------- kernel A: elementwise precompute + transposes -------------
__global__ __launch_bounds__(256) void precompute_kernel(
    Sched sc, int E,
    const int* __restrict__ user_id, const int* __restrict__ question_id,
    const float* __restrict__ priori, const float* __restrict__ condi_p,
    const float* __restrict__ condi_n, const float* __restrict__ item_diff,
    const float* __restrict__ item_disc, const float* __restrict__ q_table)
{
    extern __shared__ float ps[];
    float* s0 = ps;            // [128][33]
    float* s1 = ps + 4224;
    float* s2 = ps + 8448;
    __shared__ int su[32], sq[32];

    const int tid = threadIdx.x;
    const int b0 = blockIdx.x * 32;

    if (tid < 32) {
        su[tid] = user_id[b0 + tid];
        sq[tid] = question_id[b0 + tid];
        g_disc[b0 + tid] = sigmoidf(item_disc[sq[tid]]);
    }
    __syncthreads();

    {
        const int r = tid >> 7;
        const int c = tid & 127;
        const bool root = sc.is_root[c] != 0;
        #pragma unroll 4
        for (int i = 0; i < 16; i++) {
            const int bl = i * 2 + r;
            const int u = su[bl];
            const int q = sq[bl];
            float bv = 1.0f;
            if (root) bv = sigmoidf(priori[(size_t)u * NUM_CONCEPT + c]);
            s0[c * 33 + bl] = bv;
            float qv = q_table[(size_t)q * NUM_CONCEPT + c];
            s1[c * 33 + bl] = sigmoidf(item_diff[(size_t)q * NUM_CONCEPT + c]) * qv;
            s2[c * 33 + bl] = qv;
        }
    }
    __syncthreads();
    {
        const int k = tid >> 5;
        const int bl = tid & 31;
        #pragma unroll 4
        for (int i = 0; i < 16; i++) {
            const int kk = i * 8 + k;
            g_baseT[(size_t)kk * BATCH + b0 + bl] = s0[kk * 33 + bl];
            g_AiT[(size_t)kk * BATCH + b0 + bl]  = s1[kk * 33 + bl];
            g_qT[(size_t)kk * BATCH + b0 + bl]   = s2[kk * 33 + bl];
        }
    }

    for (int cidx = 0; cidx < 3; cidx++) {
        __syncthreads();
        {
            const int r = tid >> 7;
            const int c = tid & 127;
            const int s = cidx * 128 + c;
            const int src = sc.src[s];
            const float iv = sc.invl[s];
            #pragma unroll 4
            for (int i = 0; i < 16; i++) {
                const int bl = i * 2 + r;
                const int u = su[bl];
                float p = 1.0f, n = 1.0f;
                if (src >= 0) {
                    p = sigmoidf(condi_p[(size_t)u * E + src]);
                    n = sigmoidf(condi_n[(size_t)u * E + src]);
                    if (iv == 0.5f) { p = sqrtf(p); n = sqrtf(n); }
                    else if (iv != 1.0f) {
                        p = __powf(p, iv);
                        n = __powf(n, iv);
                    }
                }
                s0[c * 33 + bl] = p;
                s1[c * 33 + bl] = n;
            }
        }
        __syncthreads();
        {
            const int k = tid >> 5;
            const int bl = tid & 31;
            #pragma unroll 4
            for (int i = 0; i < 16; i++) {
                const int s = cidx * 128 + i * 8 + k;
                g_cpP[(size_t)s * BATCH + b0 + bl] = s0[(i * 8 + k) * 33 + bl];
                g_cnP[(size_t)s * BATCH + b0 + bl] = s1[(i * 8 + k) * 33 + bl];
            }
        }
    }
}

// ---------------- kernel B: branchless DAG ----------------------------------
__global__ __launch_bounds__(64) void dag_kernel(DagG dg)
{
    __shared__ float post[NUM_CONCEPT * 64];
    const int tid = threadIdx.x;
    const int b = blockIdx.x * 64 + tid;

    post[tid] = 0.0f;

    #pragma unroll 8
    for (int k = 0; k < NUM_CONCEPT; k++) {
        float pk = g_baseT[(size_t)k * BATCH + b];
        #pragma unroll
        for (int j = 0; j < 3; j++) {
            float pr = post[(int)dg.pred[k][j] * 64 + tid];
            float cp = g_cpP[(size_t)(k * 3 + j) * BATCH + b];
            float cn = g_cnP[(size_t)(k * 3 + j) * BATCH + b];
            pk *= cn + pr * (cp - cn);
        }
        post[k * 64 + tid] = pk;
        g_AuT[(size_t)k * BATCH + b] = pk * g_qT[(size_t)k * BATCH + b];
    }
}

// ---------------- kernel C: dual tf32 GEMM layer 1 (BM=64, Kc=32, db) -------
// buffer layout (floats): sAu[32][72] | sAi[32][72] | sWu[64][36] | sWi[64][36]
#define G1_BUF 9216
__global__ __launch_bounds__(256, 2) void gemm_layer1(
    const float* __restrict__ Wu, const float* __restrict__ Wi,
    const float* __restrict__ bu, const float* __restrict__ bi)
{
    extern __shared__ float smem[];
    const int tid = threadIdx.x;
    const int lane = tid & 31;
    const int wid = tid >> 5;
    const int wm = wid & 3;            // 4 warps -> m (64)
    const int wn = wid >> 2;           // 2 warps -> n (64)
    const int r = lane >> 2;
    const int cq = lane & 3;
    const int m0 = blockIdx.x * 64;
    const int n0 = blockIdx.y * 64;

    float accU[4][4], accI[4][4];
    #pragma unroll
    for (int ni = 0; ni < 4; ni++)
        #pragma unroll
        for (int t = 0; t < 4; t++) { accU[ni][t] = 0.f; accI[ni][t] = 0.f; }

    // ---- staging (cp.async) ----
    auto stage = [&](int kc, int fb) {
        float* b = smem + fb * G1_BUF;
        #pragma unroll
        for (int rr = 0; rr < 2; rr++) {
            int idx = tid + 256 * rr;          // 0..511
            int k = idx >> 4, mv = idx & 15;
            cpa16(b + k * 72 + mv * 4,
                  &g_AuT[(size_t)(kc * 32 + k) * BATCH + m0 + mv * 4]);
            cpa16(b + 2304 + k * 72 + mv * 4,
                  &g_AiT[(size_t)(kc * 32 + k) * BATCH + m0 + mv * 4]);
            int n = idx >> 3, kq = idx & 7;
            cpa16(b + 4608 + n * 36 + kq * 4,
                  &Wu[(size_t)(n0 + n) * NUM_CONCEPT + kc * 32 + kq * 4]);
            cpa16(b + 6912 + n * 36 + kq * 4,
                  &Wi[(size_t)(n0 + n) * NUM_CONCEPT + kc * 32 + kq * 4]);
        }
        CP_COMMIT();
    };

    stage(0, 0);
    int buf = 0;
    for (int kc = 0; kc < 4; kc++) {
        CP_WAIT0();
        __syncthreads();
        if (kc + 1 < 4) stage(kc + 1, buf ^ 1);

        float* sAu = smem + buf * G1_BUF;
        float* sAi = sAu + 2304;
        float* sWu = sAu + 4608;
        float* sWi = sAu + 6912;
        const int m = wm * 16 + r;

        #pragma unroll
        for (int kk = 0; kk < 32; kk += 8) {
            unsigned aU[4], aI[4], bU[4][2], bI[4][2];
            const float* p0 = &sAu[(kk + cq) * 72 + m];
            const float* p1 = &sAu[(kk + 4 + cq) * 72 + m];
            aU[0] = __float_as_uint(p0[0]);
            aU[1] = __float_as_uint(p0[8]);
            aU[2] = __float_as_uint(p1[0]);
            aU[3] = __float_as_uint(p1[8]);
            const float* q0 = &sAi[(kk + cq) * 72 + m];
            const float* q1 = &sAi[(kk + 4 + cq) * 72 + m];
            aI[0] = __float_as_uint(q0[0]);
            aI[1] = __float_as_uint(q0[8]);
            aI[2] = __float_as_uint(q1[0]);
            aI[3] = __float_as_uint(q1[8]);
            #pragma unroll
            for (int ni = 0; ni < 4; ni++) {
                int n = wn * 32 + ni * 8 + r;
                bU[ni][0] = __float_as_uint(sWu[n * 36 + kk + cq]);
                bU[ni][1] = __float_as_uint(sWu[n * 36 + kk + 4 + cq]);
                bI[ni][0] = __float_as_uint(sWi[n * 36 + kk + cq]);
                bI[ni][1] = __float_as_uint(sWi[n * 36 + kk + 4 + cq]);
            }
            #pragma unroll
            for (int ni = 0; ni < 4; ni++) {
                mma_tf32(accU[ni], aU, bU[ni]);
                mma_tf32(accI[ni], aI, bI[ni]);
            }
        }
        buf ^= 1;
    }

    // epilogue: x = (tanh(u+bu) - sigmoid(i+bi)) * disc, transpose via smem
    float* sX = smem;   // [64 n][68]
    {
        const int ml0 = wm * 16 + r;
        const int ml1 = ml0 + 8;
        const float d0 = g_disc[m0 + ml0];
        const float d1 = g_disc[m0 + ml1];
        #pragma unroll
        for (int ni = 0; ni < 4; ni++) {
            int nl0 = wn * 32 + ni * 8 + 2 * cq;
            int nl1 = nl0 + 1;
            float bu0 = bu[n0 + nl0], bu1 = bu[n0 + nl1];
            float bi0 = bi[n0 + nl0], bi1 = bi[n0 + nl1];
            float* aU = accU[ni];
            float* aI = accI[ni];
            sX[nl0 * 68 + ml0] = (tanhf(aU[0] + bu0) - sigmoidf(aI[0] + bi0)) * d0;
            sX[nl1 * 68 + ml0] = (tanhf(aU[1] + bu1) - sigmoidf(aI[1] + bi1)) * d0;
            sX[nl0 * 68 + ml1] = (tanhf(aU[2] + bu0) - sigmoidf(aI[2] + bi0)) * d1;
            sX[nl1 * 68 + ml1] = (tanhf(aU[3] + bu1) - sigmoidf(aI[3] + bi1)) * d1;
        }
    }
    __syncthreads();
    #pragma unroll
    for (int rr = 0; rr < 4; rr++) {
        int idx = tid + 256 * rr;          // 0..1023
        int n = idx >> 4, mq = idx & 15;
        *(float4*)&g_XT[(size_t)(n0 + n) * BATCH + m0 + mq * 4] =
            *(const float4*)&sX[n * 68 + mq * 4];
    }
}

// ---------------- kernel D: tf32 GEMM layer 2 (BM=128, Kc=64, db) -----------
// buffer layout: sA[64][136] | sW[64][68]
#define G2_BUF 13056
__global__ __launch_bounds__(256, 2) void gemm_layer2(
    const float* __restrict__ W1, const float* __restrict__ b1)
{
    extern __shared__ float smem[];
    const int tid = threadIdx.x;
    const int lane = tid & 31;
    const int wid = tid >> 5;
    const int wm = wid & 3;
    const int wn = wid >> 2;
    const int r = lane >> 2;
    const int cq = lane & 3;
    const int m0 = blockIdx.x * 128;
    const int n0 = blockIdx.y * 64;

    float acc[2][4][4];
    #pragma unroll
    for (int mi = 0; mi < 2; mi++)
        #pragma unroll
        for (int ni = 0; ni < 4; ni++)
            #pragma unroll
            for (int t = 0; t < 4; t++) acc[mi][ni][t] = 0.f;

    auto stage = [&](int kc, int fb) {
        float* b = smem + fb * G2_BUF;
        #pragma unroll
        for (int rr = 0; rr < 8; rr++) {
            int idx = tid + 256 * rr;          // 0..2047
            int k = idx >> 5, mq = idx & 31;
            cpa16(b + k * 136 + mq * 4,
                  &g_XT[(size_t)(kc * 64 + k) * BATCH + m0 + mq * 4]);
        }
        #pragma unroll
        for (int rr = 0; rr < 4; rr++) {
            int idx = tid + 256 * rr;          // 0..1023
            int n = idx >> 4, kq = idx & 15;
            cpa16(b + 8704 + n * 68 + kq * 4,
                  &W1[(size_t)(n0 + n) * DIM_HIDDEN + kc * 64 + kq * 4]);
        }
        CP_COMMIT();
    };

    stage(0, 0);
    int buf = 0;
    for (int kc = 0; kc < 8; kc++) {
        CP_WAIT0();
        __syncthreads();
        if (kc + 1 < 8) stage(kc + 1, buf ^ 1);

        float* sA = smem + buf * G2_BUF;
        float* sW = sA + 8704;

        #pragma unroll
        for (int kk = 0; kk < 64; kk += 8) {
            unsigned a[2][4], b[4][2];
            #pragma unroll
            for (int mi = 0; mi < 2; mi++) {
                int m = wm * 32 + mi * 16 + r;
                const float* p0 = &sA[(kk + cq) * 136 + m];
                const float* p1 = &sA[(kk + 4 + cq) * 136 + m];
                a[mi][0] = __float_as_uint(p0[0]);
                a[mi][1] = __float_as_uint(p0[8]);
                a[mi][2] = __float_as_uint(p1[0]);
                a[mi][3] = __float_as_uint(p1[8]);
            }
            #pragma unroll
            for (int ni = 0; ni < 4; ni++) {
                int n = wn * 32 + ni * 8 + r;
                b[ni][0] = __float_as_uint(sW[n * 68 + kk + cq]);
                b[ni][1] = __float_as_uint(sW[n * 68 + kk + 4 + cq]);
            }
            #pragma unroll
            for (int mi = 0; mi < 2; mi++)
                #pragma unroll
                for (int ni = 0; ni < 4; ni++)
                    mma_tf32(acc[mi][ni], a[mi], b[ni]);
        }
        buf ^= 1;
    }

    #pragma unroll
    for (int mi = 0; mi < 2; mi++) {
        int mg0 = m0 + wm * 32 + mi * 16 + r;
        int mg1 = mg0 + 8;
        #pragma unroll
        for (int ni = 0; ni < 4; ni++) {
            int ng = n0 + wn * 32 + ni * 8 + 2 * cq;
            float b0 = b1[ng], b1v = b1[ng + 1];
            float* a = acc[mi][ni];
            float2 v0 = make_float2(sigmoidf(a[0] + b0), sigmoidf(a[1] + b1v));
            float2 v1 = make_float2(sigmoidf(a[2] + b0), sigmoidf(a[3] + b1v));
            *(float2*)&g_H[(size_t)mg0 * H2 + ng] = v0;
            *(float2*)&g_H[(size_t)mg1 * H2 + ng] = v1;
        }
    }
}

// ---------------- kernel E: final matvec (256 -> 1) + sigmoid ---------------
__global__ __launch_bounds__(256) void final_kernel(
    const float* __restrict__ W2, const float* __restrict__ b2,
    float* __restrict__ out)
{
    __shared__ float w[H2];
    const int tid = threadIdx.x;
    const int lane = tid & 31;
    const int wid = tid >> 5;
    w[tid] = W2[tid];
    __syncthreads();
    const int m = blockIdx.x * 8 + wid;
    const float4* hp = (const float4*)(g_H + (size_t)m * H2);
    float s = 0.f;
    #pragma unroll
    for (int i = 0; i < 2; i++) {
        int idx = lane * 2 + i;
        float4 v = hp[idx];
        int k = idx * 4;
        s += v.x * w[k] + v.y * w[k + 1] + v.z * w[k + 2] + v.w * w[k + 3];
    }
    #pragma unroll
    for (int off = 16; off > 0; off >>= 1)
        s += __shfl_xor_sync(0xffffffffu, s, off);
    if (lane == 0) out[m] = sigmoidf(s + b2[0]);
}

// ---------------- launch -----------------------------------------------------
extern "C" void kernel_launch(void* const* d_in, const int* in_sizes, int n_in,
                              void* d_out, int out_size)
{
    Graph g;
    Sched sc;
    DagG dg;
    build_graph(g, sc, dg);

    const int*   user_id     = (const int*)d_in[0];
    const int*   question_id = (const int*)d_in[1];
    const float* priori      = (const float*)d_in[2];
    const float* condi_p     = (const float*)d_in[3];
    const float* condi_n     = (const float*)d_in[4];
    const float* item_diff   = (const float*)d_in[5];
    const float* item_disc   = (const float*)d_in[6];
    const float* q_table     = (const float*)d_in[7];
    const float* Wu          = (const float*)d_in[8];
    const float* bu          = (const float*)d_in[9];
    const float* Wi          = (const float*)d_in[10];
    const float* bi          = (const float*)d_in[11];
    const float* W1          = (const float*)d_in[12];
    const float* b1          = (const float*)d_in[13];
    const float* W2          = (const float*)d_in[14];
    const float* b2          = (const float*)d_in[15];
    float* out = (float*)d_out;

    const int E = in_sizes[3] / NUM_USER;

    cudaFuncSetAttribute(precompute_kernel, cudaFuncAttributeMaxDynamicSharedMemorySize, 50688);
    cudaFuncSetAttribute(gemm_layer1, cudaFuncAttributeMaxDynamicSharedMemorySize, 2 * G1_BUF * 4);
    cudaFuncSetAttribute(gemm_layer2, cudaFuncAttributeMaxDynamicSharedMemorySize, 2 * G2_BUF * 4);

    precompute_kernel<<<BATCH / 32, 256, 50688>>>(sc, E, user_id, question_id, priori,
                                                  condi_p, condi_n, item_diff,
                                                  item_disc, q_table);

    dag_kernel<<<BATCH / 64, 64>>>(dg);

    dim3 grid1(BATCH / 64, DIM_HIDDEN / 64);
    gemm_layer1<<<grid1, 256, 2 * G1_BUF * 4>>>(Wu, Wi, bu, bi);

    dim3 grid2(BATCH / 128, H2 / 64);
    gemm_layer2<<<grid2, 256, 2 * G2_BUF * 4>>>(W1, b1);

    final_kernel<<<BATCH / 8, 256>>>(W2, b2, out);
}

// round 6
// speedup vs baseline: 1.2210x; 1.0508x over previous
#include <cuda_runtime.h>
#include <cuda_bf16.h>
#include <cstdint>

#define NUM_USER 200000
#define NUM_QUESTION 20000
#define NUM_CONCEPT 128
#define DIM_HIDDEN 512
#define H2 256
#define BATCH 16384
#define EMAX 400

// ---------------- scratch (device globals; no allocations allowed) ----------
__device__ float g_AuT[NUM_CONCEPT * BATCH];   // post*q, feature-major
__device__ float g_AiT[NUM_CONCEPT * BATCH];   // sigmoid(diff)*q, feature-major
__device__ float g_disc[BATCH];
__device__ float g_XT[DIM_HIDDEN * BATCH];     // layer-1 out, feature-major
__device__ float g_H[BATCH * H2];              // layer-2 out, row-major

// ---------------- graph structure (replicated numpy RandomState(0)) ---------
struct Graph {
    int E;
    unsigned char lp[NUM_CONCEPT];
    short off[NUM_CONCEPT];
    unsigned char pred[NUM_CONCEPT][3];
};
struct EdgeParams {
    float invl[EMAX];
};

struct MT19937 {
    uint32_t mt[624];
    int mti;
    void seed(uint32_t s) {
        mt[0] = s;
        for (int i = 1; i < 624; i++)
            mt[i] = 1812433253u * (mt[i - 1] ^ (mt[i - 1] >> 30)) + (uint32_t)i;
        mti = 624;
    }
    uint32_t next() {
        if (mti >= 624) {
            for (int i = 0; i < 624; i++) {
                uint32_t y = (mt[i] & 0x80000000u) | (mt[(i + 1) % 624] & 0x7fffffffu);
                uint32_t v = mt[(i + 397) % 624] ^ (y >> 1);
                if (y & 1u) v ^= 0x9908b0dfu;
                mt[i] = v;
            }
            mti = 0;
        }
        uint32_t y = mt[mti++];
        y ^= y >> 11;
        y ^= (y << 7) & 0x9d2c5680u;
        y ^= (y << 15) & 0xefc60000u;
        y ^= y >> 18;
        return y;
    }
    uint32_t interval(uint32_t mx) {
        if (mx == 0) return 0;
        uint32_t mask = mx;
        mask |= mask >> 1; mask |= mask >> 2; mask |= mask >> 4;
        mask |= mask >> 8; mask |= mask >> 16;
        uint32_t v;
        do { v = next() & mask; } while (v > mx);
        return v;
    }
};

static void build_graph(Graph& g, EdgeParams& ep) {
    MT19937 r;
    r.seed(0u);
    int E = 0;
    for (int k = 0; k < NUM_CONCEPT; k++) {
        int l = 0;
        if (k > 0) {
            int hi = (k < 3) ? k : 3;
            l = (int)r.interval((uint32_t)hi);
        }
        g.lp[k] = (unsigned char)l;
        g.off[k] = (short)E;
        g.pred[k][0] = g.pred[k][1] = g.pred[k][2] = 0;
        if (l > 0) {
            int perm[NUM_CONCEPT];
            for (int i = 0; i < k; i++) perm[i] = i;
            for (int i = k - 1; i >= 1; i--) {
                int j = (int)r.interval((uint32_t)i);
                int t = perm[i]; perm[i] = perm[j]; perm[j] = t;
            }
            int p[3];
            for (int j = 0; j < l; j++) p[j] = perm[j];
            for (int a = 0; a < l; a++)
                for (int b = a + 1; b < l; b++)
                    if (p[b] < p[a]) { int t = p[a]; p[a] = p[b]; p[b] = t; }
            for (int j = 0; j < l; j++) {
                g.pred[k][j] = (unsigned char)p[j];
                ep.invl[E + j] = 1.0f / (float)l;
            }
        }
        E += l;
    }
    g.E = E;
}

// ---------------- device helpers --------------------------------------------
__device__ __forceinline__ float sigmoidf(float x) {
    return 1.0f / (1.0f + __expf(-x));
}
__device__ __forceinline__ void mma_tf32(float* c, const unsigned* a, const unsigned* b) {
    asm volatile(
        "mma.sync.aligned.m16n8k8.row.col.f32.tf32.tf32.f32 "
        "{%0,%1,%2,%3}, {%4,%5,%6,%7}, {%8,%9}, {%0,%1,%2,%3};\n"
        : "+f"(c[0]), "+f"(c[1]), "+f"(c[2]), "+f"(c[3])
        : "r"(a[0]), "r"(a[1]), "r"(a[2]), "r"(a[3]), "r"(b[0]), "r"(b[1]));
}
__device__ __forceinline__ void cpa16(float* dst_smem, const float* src) {
    unsigned a = (unsigned)__cvta_generic_to_shared(dst_smem);
    asm volatile("cp.async.ca.shared.global [%0], [%1], 16;" :: "r"(a), "l"(src));
}
#define CP_COMMIT() asm volatile("cp.async.commit_group;")
#define CP_WAIT0()  asm volatile("cp.async.wait_group 0;" ::: "memory")

// ---------------- kernel A: fused precompute + DAG --------------------------
// 256 threads handle 32 batch elements end-to-end; everything stays in smem.
// smem layout (floats): bp[128][33] | q[128][33] | px[128][33] | cp[E][33] | cn[E][33]
__global__ __launch_bounds__(256) void fused_pre_dag(
    Graph g, EdgeParams ep,
    const int* __restrict__ user_id, const int* __restrict__ question_id,
    const float* __restrict__ priori, const float* __restrict__ condi_p,
    const float* __restrict__ condi_n, const float* __restrict__ item_diff,
    const float* __restrict__ item_disc, const float* __restrict__ q_table)
{
    extern __shared__ float sm[];
    const int E = g.E;
    float* bp = sm;                    // sigmoid(priori) [k][bl]
    float* sq2 = sm + 4224;            // q [k][bl]
    float* px = sm + 8448;             // ai staging, then post [k][bl]
    float* cp = sm + 12672;            // [e][bl]
    float* cn = cp + E * 33;

    __shared__ int su[32], squ[32];

    const int tid = threadIdx.x;
    const int lane = tid & 31;
    const int wid = tid >> 5;
    const int b0 = blockIdx.x * 32;

    if (tid < 32) {
        su[tid] = user_id[b0 + tid];
        squ[tid] = question_id[b0 + tid];
        g_disc[b0 + tid] = sigmoidf(item_disc[squ[tid]]);
    }
    __syncthreads();

    // ---- phase 1: bp / q / ai(staged in px) ----
    {
        const int r = tid >> 7;          // 0/1
        const int c = tid & 127;
        #pragma unroll 4
        for (int i = 0; i < 16; i++) {
            const int bl = i * 2 + r;
            const int u = su[bl];
            const int qq = squ[bl];
            bp[c * 33 + bl] = sigmoidf(priori[(size_t)u * NUM_CONCEPT + c]);
            float qv = q_table[(size_t)qq * NUM_CONCEPT + c];
            sq2[c * 33 + bl] = qv;
            px[c * 33 + bl] = sigmoidf(item_diff[(size_t)qq * NUM_CONCEPT + c]) * qv;
        }
    }
    __syncthreads();
    // flush AiT (px holds ai), coalesced 128B stores
    {
        const int k = tid >> 5;
        const int bl = tid & 31;
        #pragma unroll 4
        for (int i = 0; i < 16; i++) {
            const int kk = i * 8 + k;
            g_AiT[(size_t)kk * BATCH + b0 + bl] = px[kk * 33 + bl];
        }
    }

    // ---- phase 2: cp / cn (actual edges only) ----
    for (int bl = 0; bl < 32; bl++) {
        const int u = su[bl];
        for (int e = tid; e < E; e += 256) {
            const float iv = ep.invl[e];
            float p = sigmoidf(condi_p[(size_t)u * E + e]);
            float n = sigmoidf(condi_n[(size_t)u * E + e]);
            if (iv == 0.5f) { p = sqrtf(p); n = sqrtf(n); }
            else if (iv != 1.0f) {
                p = __powf(p, iv);
                n = __powf(n, iv);
            }
            cp[e * 33 + bl] = p;
            cn[e * 33 + bl] = n;
        }
    }
    __syncthreads();   // also orders AiT flush before px reuse

    // ---- phase 3: DAG recurrence on warp 0 (px becomes post) ----
    if (wid == 0) {
        const int bl = lane;
        for (int k = 0; k < NUM_CONCEPT; k++) {
            const int l = g.lp[k];
            float pk;
            if (l == 0) {
                pk = bp[k * 33 + bl];
            } else {
                const int o = g.off[k];
                pk = 1.0f;
                #pragma unroll 3
                for (int j = 0; j < 3; j++) {
                    if (j >= l) break;
                    float pr = px[(int)g.pred[k][j] * 33 + bl];
                    float p = cp[(o + j) * 33 + bl];
                    float n = cn[(o + j) * 33 + bl];
                    pk *= n + pr * (p - n);
                }
            }
            px[k * 33 + bl] = pk;
        }
    }
    __syncthreads();

    // ---- phase 4: AuT = post * q, coalesced ----
    {
        const int k = tid >> 5;
        const int bl = tid & 31;
        #pragma unroll 4
        for (int i = 0; i < 16; i++) {
            const int kk = i * 8 + k;
            g_AuT[(size_t)kk * BATCH + b0 + bl] =
                px[kk * 33 + bl] * sq2[kk * 33 + bl];
        }
    }
}

// ---------------- kernel C: dual tf32 GEMM layer 1 (BM=64, Kc=32, db) -------
#define G1_BUF 9216
__global__ __launch_bounds__(256, 2) void gemm_layer1(
    const float* __restrict__ Wu, const float* __restrict__ Wi,
    const float* __restrict__ bu, const float* __restrict__ bi)
{
    extern __shared__ float smem[];
    const int tid = threadIdx.x;
    const int lane = tid & 31;
    const int wid = tid >> 5;
    const int wm = wid & 3;
    const int wn = wid >> 2;
    const int r = lane >> 2;
    const int cq = lane & 3;
    const int m0 = blockIdx.x * 64;
    const int n0 = blockIdx.y * 64;

    float accU[4][4], accI[4][4];
    #pragma unroll
    for (int ni = 0; ni < 4; ni++)
        #pragma unroll
        for (int t = 0; t < 4; t++) { accU[ni][t] = 0.f; accI[ni][t] = 0.f; }

    auto stage = [&](int kc, int fb) {
        float* b = smem + fb * G1_BUF;
        #pragma unroll
        for (int rr = 0; rr < 2; rr++) {
            int idx = tid + 256 * rr;
            int k = idx >> 4, mv = idx & 15;
            cpa16(b + k * 72 + mv * 4,
                  &g_AuT[(size_t)(kc * 32 + k) * BATCH + m0 + mv * 4]);
            cpa16(b + 2304 + k * 72 + mv * 4,
                  &g_AiT[(size_t)(kc * 32 + k) * BATCH + m0 + mv * 4]);
            int n = idx >> 3, kq = idx & 7;
            cpa16(b + 4608 + n * 36 + kq * 4,
                  &Wu[(size_t)(n0 + n) * NUM_CONCEPT + kc * 32 + kq * 4]);
            cpa16(b + 6912 + n * 36 + kq * 4,
                  &Wi[(size_t)(n0 + n) * NUM_CONCEPT + kc * 32 + kq * 4]);
        }
        CP_COMMIT();
    };

    stage(0, 0);
    int buf = 0;
    for (int kc = 0; kc < 4; kc++) {
        CP_WAIT0();
        __syncthreads();
        if (kc + 1 < 4) stage(kc + 1, buf ^ 1);

        float* sAu = smem + buf * G1_BUF;
        float* sAi = sAu + 2304;
        float* sWu = sAu + 4608;
        float* sWi = sAu + 6912;
        const int m = wm * 16 + r;

        #pragma unroll
        for (int kk = 0; kk < 32; kk += 8) {
            unsigned aU[4], aI[4], bU[4][2], bI[4][2];
            const float* p0 = &sAu[(kk + cq) * 72 + m];
            const float* p1 = &sAu[(kk + 4 + cq) * 72 + m];
            aU[0] = __float_as_uint(p0[0]);
            aU[1] = __float_as_uint(p0[8]);
            aU[2] = __float_as_uint(p1[0]);
            aU[3] = __float_as_uint(p1[8]);
            const float* q0 = &sAi[(kk + cq) * 72 + m];
            const float* q1 = &sAi[(kk + 4 + cq) * 72 + m];
            aI[0] = __float_as_uint(q0[0]);
            aI[1] = __float_as_uint(q0[8]);
            aI[2] = __float_as_uint(q1[0]);
            aI[3] = __float_as_uint(q1[8]);
            #pragma unroll
            for (int ni = 0; ni < 4; ni++) {
                int n = wn * 32 + ni * 8 + r;
                bU[ni][0] = __float_as_uint(sWu[n * 36 + kk + cq]);
                bU[ni][1] = __float_as_uint(sWu[n * 36 + kk + 4 + cq]);
                bI[ni][0] = __float_as_uint(sWi[n * 36 + kk + cq]);
                bI[ni][1] = __float_as_uint(sWi[n * 36 + kk + 4 + cq]);
            }
            #pragma unroll
            for (int ni = 0; ni < 4; ni++) {
                mma_tf32(accU[ni], aU, bU[ni]);
                mma_tf32(accI[ni], aI, bI[ni]);
            }
        }
        buf ^= 1;
    }

    float* sX = smem;   // [64 n][68]
    {
        const int ml0 = wm * 16 + r;
        const int ml1 = ml0 + 8;
        const float d0 = g_disc[m0 + ml0];
        const float d1 = g_disc[m0 + ml1];
        #pragma unroll
        for (int ni = 0; ni < 4; ni++) {
            int nl0 = wn * 32 + ni * 8 + 2 * cq;
            int nl1 = nl0 + 1;
            float bu0 = bu[n0 + nl0], bu1 = bu[n0 + nl1];
            float bi0 = bi[n0 + nl0], bi1 = bi[n0 + nl1];
            float* aU = accU[ni];
            float* aI = accI[ni];
            sX[nl0 * 68 + ml0] = (tanhf(aU[0] + bu0) - sigmoidf(aI[0] + bi0)) * d0;
            sX[nl1 * 68 + ml0] = (tanhf(aU[1] + bu1) - sigmoidf(aI[1] + bi1)) * d0;
            sX[nl0 * 68 + ml1] = (tanhf(aU[2] + bu0) - sigmoidf(aI[2] + bi0)) * d1;
            sX[nl1 * 68 + ml1] = (tanhf(aU[3] + bu1) - sigmoidf(aI[3] + bi1)) * d1;
        }
    }
    __syncthreads();
    #pragma unroll
    for (int rr = 0; rr < 4; rr++) {
        int idx = tid + 256 * rr;
        int n = idx >> 4, mq = idx & 15;
        *(float4*)&g_XT[(size_t)(n0 + n) * BATCH + m0 + mq * 4] =
            *(const float4*)&sX[n * 68 + mq * 4];
    }
}

// ---------------- kernel D: tf32 GEMM layer 2 (BM=128, Kc=64, db) -----------
#define G2_BUF 13056
__global__ __launch_bounds__(256, 2) void gemm_layer2(
    const float* __restrict__ W1, const float* __restrict__ b1)
{
    extern __shared__ float smem[];
    const int tid = threadIdx.x;
    const int lane = tid & 31;
    const int wid = tid >> 5;
    const int wm = wid & 3;
    const int wn = wid >> 2;
    const int r = lane >> 2;
    const int cq = lane & 3;
    const int m0 = blockIdx.x * 128;
    const int n0 = blockIdx.y * 64;

    float acc[2][4][4];
    #pragma unroll
    for (int mi = 0; mi < 2; mi++)
        #pragma unroll
        for (int ni = 0; ni < 4; ni++)
            #pragma unroll
            for (int t = 0; t < 4; t++) acc[mi][ni][t] = 0.f;

    auto stage = [&](int kc, int fb) {
        float* b = smem + fb * G2_BUF;
        #pragma unroll
        for (int rr = 0; rr < 8; rr++) {
            int idx = tid + 256 * rr;
            int k = idx >> 5, mq = idx & 31;
            cpa16(b + k * 136 + mq * 4,
                  &g_XT[(size_t)(kc * 64 + k) * BATCH + m0 + mq * 4]);
        }
        #pragma unroll
        for (int rr = 0; rr < 4; rr++) {
            int idx = tid + 256 * rr;
            int n = idx >> 4, kq = idx & 15;
            cpa16(b + 8704 + n * 68 + kq * 4,
                  &W1[(size_t)(n0 + n) * DIM_HIDDEN + kc * 64 + kq * 4]);
        }
        CP_COMMIT();
    };

    stage(0, 0);
    int buf = 0;
    for (int kc = 0; kc < 8; kc++) {
        CP_WAIT0();
        __syncthreads();
        if (kc + 1 < 8) stage(kc + 1, buf ^ 1);

        float* sA = smem + buf * G2_BUF;
        float* sW = sA + 8704;

        #pragma unroll
        for (int kk = 0; kk < 64; kk += 8) {
            unsigned a[2][4], b[4][2];
            #pragma unroll
            for (int mi = 0; mi < 2; mi++) {
                int m = wm * 32 + mi * 16 + r;
                const float* p0 = &sA[(kk + cq) * 136 + m];
                const float* p1 = &sA[(kk + 4 + cq) * 136 + m];
                a[mi][0] = __float_as_uint(p0[0]);
                a[mi][1] = __float_as_uint(p0[8]);
                a[mi][2] = __float_as_uint(p1[0]);
                a[mi][3] = __float_as_uint(p1[8]);
            }
            #pragma unroll
            for (int ni = 0; ni < 4; ni++) {
                int n = wn * 32 + ni * 8 + r;
                b[ni][0] = __float_as_uint(sW[n * 68 + kk + cq]);
                b[ni][1] = __float_as_uint(sW[n * 68 + kk + 4 + cq]);
            }
            #pragma unroll
            for (int mi = 0; mi < 2; mi++)
                #pragma unroll
                for (int ni = 0; ni < 4; ni++)
                    mma_tf32(acc[mi][ni], a[mi], b[ni]);
        }
        buf ^= 1;
    }

    #pragma unroll
    for (int mi = 0; mi < 2; mi++) {
        int mg0 = m0 + wm * 32 + mi * 16 + r;
        int mg1 = mg0 + 8;
        #pragma unroll
        for (int ni = 0; ni < 4; ni++) {
            int ng = n0 + wn * 32 + ni * 8 + 2 * cq;
            float b0 = b1[ng], b1v = b1[ng + 1];
            float* a = acc[mi][ni];
            float2 v0 = make_float2(sigmoidf(a[0] + b0), sigmoidf(a[1] + b1v));
            float2 v1 = make_float2(sigmoidf(a[2] + b0), sigmoidf(a[3] + b1v));
            *(float2*)&g_H[(size_t)mg0 * H2 + ng] = v0;
            *(float2*)&g_H[(size_t)mg1 * H2 + ng] = v1;
        }
    }
}

// ---------------- kernel E: final matvec (256 -> 1) + sigmoid ---------------
__global__ __launch_bounds__(256) void final_kernel(
    const float* __restrict__ W2, const float* __restrict__ b2,
    float* __restrict__ out)
{
    __shared__ float w[H2];
    const int tid = threadIdx.x;
    const int lane = tid & 31;
    const int wid = tid >> 5;
    w[tid] = W2[tid];
    __syncthreads();
    const int m = blockIdx.x * 8 + wid;
    const float4* hp = (const float4*)(g_H + (size_t)m * H2);
    float s = 0.f;
    #pragma unroll
    for (int i = 0; i < 2; i++) {
        int idx = lane * 2 + i;
        float4 v = hp[idx];
        int k = idx * 4;
        s += v.x * w[k] + v.y * w[k + 1] + v.z * w[k + 2] + v.w * w[k + 3];
    }
    #pragma unroll
    for (int off = 16; off > 0; off >>= 1)
        s += __shfl_xor_sync(0xffffffffu, s, off);
    if (lane == 0) out[m] = sigmoidf(s + b2[0]);
}

// ---------------- launch -----------------------------------------------------
extern "C" void kernel_launch(void* const* d_in, const int* in_sizes, int n_in,
                              void* d_out, int out_size)
{
    Graph g;
    EdgeParams ep;
    build_graph(g, ep);

    const int*   user_id     = (const int*)d_in[0];
    const int*   question_id = (const int*)d_in[1];
    const float* priori      = (const float*)d_in[2];
    const float* condi_p     = (const float*)d_in[3];
    const float* condi_n     = (const float*)d_in[4];
    const float* item_diff   = (const float*)d_in[5];
    const float* item_disc   = (const float*)d_in[6];
    const float* q_table     = (const float*)d_in[7];
    const float* Wu          = (const float*)d_in[8];
    const float* bu          = (const float*)d_in[9];
    const float* Wi          = (const float*)d_in[10];
    const float* bi          = (const float*)d_in[11];
    const float* W1          = (const float*)d_in[12];
    const float* b1          = (const float*)d_in[13];
    const float* W2          = (const float*)d_in[14];
    const float* b2          = (const float*)d_in[15];
    float* out = (float*)d_out;

    // smem for fused kernel: (3*128*33 + 2*E*33) floats
    const int fusedSmem = (3 * NUM_CONCEPT * 33 + 2 * g.E * 33) * 4;

    cudaFuncSetAttribute(fused_pre_dag, cudaFuncAttributeMaxDynamicSharedMemorySize, 160000);
    cudaFuncSetAttribute(gemm_layer1, cudaFuncAttributeMaxDynamicSharedMemorySize, 2 * G1_BUF * 4);
    cudaFuncSetAttribute(gemm_layer2, cudaFuncAttributeMaxDynamicSharedMemorySize, 2 * G2_BUF * 4);

    fused_pre_dag<<<BATCH / 32, 256, fusedSmem>>>(g, ep, user_id, question_id,
                                                  priori, condi_p, condi_n,
                                                  item_diff, item_disc, q_table);

    dim3 grid1(BATCH / 64, DIM_HIDDEN / 64);
    gemm_layer1<<<grid1, 256, 2 * G1_BUF * 4>>>(Wu, Wi, bu, bi);

    dim3 grid2(BATCH / 128, H2 / 64);
    gemm_layer2<<<grid2, 256, 2 * G2_BUF * 4>>>(W1, b1);

    final_kernel<<<BATCH / 8, 256>>>(W2, b2, out);
}